// round 1
// baseline (speedup 1.0000x reference)
#include <cuda_runtime.h>
#include <cuda_bf16.h>

#define N_TOK   2048
#define IN_F    2048
#define OUT_F   2048
#define BLOCK   32
#define IBLK    64
#define OBLK    64
#define NNZ     1228
#define TILE_T  128
#define THREADS 256

// CSR row pointers for the sorted oi array (built on device each launch;
// deterministic, graph-capturable, no allocations).
__device__ int g_row_ptr[OBLK + 1];

__global__ void build_rowptr_kernel(const int* __restrict__ oi) {
    int b = threadIdx.x;
    if (b <= OBLK) {
        int cnt = 0;
        for (int k = 0; k < NNZ; ++k) cnt += (oi[k] < b) ? 1 : 0;
        g_row_ptr[b] = cnt;
    }
}

// One CTA = (128-token tile) x (one 32-wide output block).
// 8 warps; lane = output column; each thread accumulates 16 tokens.
__global__ __launch_bounds__(THREADS, 4) void bsmm_kernel(
    const float* __restrict__ x,
    const float* __restrict__ w,
    const int*   __restrict__ ii,
    float*       __restrict__ y)
{
    __shared__ float ws[32 * 33];        // w block, [o][i] with pad 33 (conflict-free column reads)
    __shared__ float xs[TILE_T * 32];    // x tile,  [t][i] (reads are warp-broadcast)

    const int ob   = blockIdx.y;
    const int t0   = blockIdx.x * TILE_T;
    const int tid  = threadIdx.x;
    const int lane = tid & 31;           // output column within block
    const int warp = tid >> 5;           // token sub-tile

    const int k0 = g_row_ptr[ob];
    const int k1 = g_row_ptr[ob + 1];

    float acc[16];
#pragma unroll
    for (int t = 0; t < 16; ++t) acc[t] = 0.0f;

    for (int k = k0; k < k1; ++k) {
        const int ib = ii[k];

        __syncthreads();   // previous iteration's smem reads done before overwrite

        // ---- load w[k] (32x32 f32 = 1024 floats): 256 threads x float4, coalesced.
        {
            const float4 v = ((const float4*)(w + (size_t)k * 1024))[tid];
            const int o  = tid >> 3;     // 8 float4 per 32-wide row
            const int iq = tid & 7;
            float* p = &ws[o * 33 + iq * 4];
            p[0] = v.x; p[1] = v.y; p[2] = v.z; p[3] = v.w;   // banks o+4*iq+c : conflict-free
        }

        // ---- load x tile: 128 tokens x 32 floats from column block ib (coalesced 128B rows)
        {
            const float* xg = x + (size_t)t0 * IN_F + (size_t)ib * 32;
            const int tt = tid >> 3;     // 0..31
            const int q  = tid & 7;      // float4 index within row
#pragma unroll
            for (int r = 0; r < 4; ++r) {
                const int trow = tt + r * 32;
                float4 v = *(const float4*)(xg + (size_t)trow * IN_F + q * 4);
                *(float4*)(&xs[trow * 32 + q * 4]) = v;
            }
        }

        __syncthreads();

        // ---- hoist this lane's w column into registers (conflict-free: bank = (lane+i)&31)
        float wr[32];
#pragma unroll
        for (int i = 0; i < 32; ++i) wr[i] = ws[lane * 33 + i];

        // ---- 16 tokens x 32-deep dot products; x reads are broadcast LDS.128
#pragma unroll
        for (int t = 0; t < 16; ++t) {
            const float4* xr = (const float4*)&xs[(warp * 16 + t) * 32];
            float s0 = 0.f, s1 = 0.f, s2 = 0.f, s3 = 0.f;
#pragma unroll
            for (int q = 0; q < 8; ++q) {
                const float4 xv = xr[q];
                s0 += xv.x * wr[4 * q + 0];
                s1 += xv.y * wr[4 * q + 1];
                s2 += xv.z * wr[4 * q + 2];
                s3 += xv.w * wr[4 * q + 3];
            }
            acc[t] += (s0 + s1) + (s2 + s3);
        }
    }

    // ---- write out (covers every output element, including zero-nnz blocks)
#pragma unroll
    for (int t = 0; t < 16; ++t) {
        const int n = t0 + warp * 16 + t;
        y[(size_t)n * OUT_F + (size_t)ob * 32 + lane] = acc[t];
    }
}

extern "C" void kernel_launch(void* const* d_in, const int* in_sizes, int n_in,
                              void* d_out, int out_size) {
    const float* x  = (const float*)d_in[0];
    const float* w  = (const float*)d_in[1];
    const int*   oi = (const int*)  d_in[2];
    const int*   ii = (const int*)  d_in[3];
    float*       y  = (float*)d_out;

    build_rowptr_kernel<<<1, 96>>>(oi);

    dim3 grid(N_TOK / TILE_T, OBLK);
    bsmm_kernel<<<grid, THREADS>>>(x, w, ii, y);
}

// round 3
// speedup vs baseline: 2.8346x; 2.8346x over previous
#include <cuda_runtime.h>
#include <cstdint>

#define N_TOK   2048
#define IN_F    2048
#define OUT_F   2048
#define OBLK    64
#define NNZ     1228
#define TILE_T  256
#define THREADS 256

#define XS_STRIDE 36                       // words per token row (pad: 144B, 16B-aligned)
#define XS_WORDS  (TILE_T * XS_STRIDE)     // 9216 words = 36864 B
#define WS_STRIDE 36                       // words per lane of fragment-ordered w
#define WS_WORDS  (32 * WS_STRIDE)         // 1152 words = 4608 B
#define SMEM_BYTES ((2 * XS_WORDS + 2 * WS_WORDS) * 4)   // 82944 B

__device__ int g_row_ptr[OBLK + 1];

__global__ void build_rowptr_kernel(const int* __restrict__ oi) {
    int b = threadIdx.x;
    if (b <= OBLK) {
        int lo = 0, hi = NNZ;
        while (lo < hi) { int m = (lo + hi) >> 1; if (oi[m] < b) lo = m + 1; else hi = m; }
        g_row_ptr[b] = lo;
    }
}

// ---------- helpers ----------
__device__ __forceinline__ uint32_t smem_u32(const void* p) {
    uint32_t a;
    asm("{ .reg .u64 t; cvta.to.shared.u64 t, %1; cvt.u32.u64 %0, t; }" : "=r"(a) : "l"(p));
    return a;
}
__device__ __forceinline__ uint32_t f2tf(float f) {
    uint32_t u; asm("cvt.rna.tf32.f32 %0, %1;" : "=r"(u) : "f"(f)); return u;
}
__device__ __forceinline__ void cp16(uint32_t dst, const void* src) {
    asm volatile("cp.async.ca.shared.global [%0], [%1], 16;" :: "r"(dst), "l"(src) : "memory");
}
__device__ __forceinline__ void cp_commit() { asm volatile("cp.async.commit_group;" ::: "memory"); }
__device__ __forceinline__ void cp_wait0()  { asm volatile("cp.async.wait_group 0;"  ::: "memory"); }

__device__ __forceinline__ void mma_tf32(float& c0, float& c1, float& c2, float& c3,
                                         uint32_t a0, uint32_t a1, uint32_t a2, uint32_t a3,
                                         uint32_t b0, uint32_t b1) {
    asm volatile("mma.sync.aligned.m16n8k8.row.col.f32.tf32.tf32.f32 "
                 "{%0,%1,%2,%3}, {%4,%5,%6,%7}, {%8,%9}, {%0,%1,%2,%3};"
                 : "+f"(c0), "+f"(c1), "+f"(c2), "+f"(c3)
                 : "r"(a0), "r"(a1), "r"(a2), "r"(a3), "r"(b0), "r"(b1));
}

// ---------- main kernel ----------
__global__ __launch_bounds__(THREADS, 2) void bsmm_mma_kernel(
    const float* __restrict__ x,
    const float* __restrict__ w,
    const int*   __restrict__ ii,
    float*       __restrict__ y)
{
    extern __shared__ float sm[];
    float* xs[2] = { sm, sm + XS_WORDS };
    uint32_t* ws[2] = { (uint32_t*)(sm + 2 * XS_WORDS),
                        (uint32_t*)(sm + 2 * XS_WORDS + WS_WORDS) };

    const int ob   = blockIdx.x;                 // ob fast-varying: balances nnz across SMs
    const int t0   = blockIdx.y * TILE_T;
    const int tid  = threadIdx.x;
    const int wid  = tid >> 5;
    const int lane = tid & 31;
    const int q    = tid & 7;                    // float4 column index (0..7)
    const int rg   = tid >> 3;                   // row group (0..31)

    const int k0 = g_row_ptr[ob];
    const int k1 = g_row_ptr[ob + 1];

    float c[2][4][4];
#pragma unroll
    for (int mt = 0; mt < 2; ++mt)
#pragma unroll
        for (int nt = 0; nt < 4; ++nt)
#pragma unroll
            for (int r = 0; r < 4; ++r) c[mt][nt][r] = 0.0f;

    // w staging indices for this thread's float4 (o = rg, i = q*4 + cc)
    const int w_o  = rg;
    const int w_nt = rg >> 3;
    int w_dst[4];
#pragma unroll
    for (int cc = 0; cc < 4; ++cc) {
        const int i  = q * 4 + cc;
        const int dl = (w_o & 7) * 4 + cc;               // dest lane
        const int j  = (i >> 3) * 8 + w_nt * 2 + ((i >> 2) & 1);
        w_dst[cc] = dl * WS_STRIDE + j;
    }

    if (k1 > k0) {
        // ---------------- prologue: stage k0 into buffer 0 ----------------
        {
            const int ib = ii[k0];
            const float* xg = x + (size_t)t0 * IN_F + (size_t)ib * 32 + q * 4;
            const uint32_t xs0 = smem_u32(xs[0]);
#pragma unroll
            for (int jr = 0; jr < 8; ++jr) {
                const int t = rg + 32 * jr;
                cp16(xs0 + (uint32_t)(t * XS_STRIDE + q * 4) * 4,
                     xg + (size_t)t * IN_F);
            }
            cp_commit();
            const float4 wv = ((const float4*)(w + (size_t)k0 * 1024))[tid];
            ws[0][w_dst[0]] = f2tf(wv.x);
            ws[0][w_dst[1]] = f2tf(wv.y);
            ws[0][w_dst[2]] = f2tf(wv.z);
            ws[0][w_dst[3]] = f2tf(wv.w);
            cp_wait0();
        }
        __syncthreads();

        // ---------------- main loop ----------------
        for (int k = k0; k < k1; ++k) {
            const int s = (k - k0) & 1;
            const bool pf = (k + 1 < k1);
            float4 wv;

            // issue next x tile (cp.async) + next w LDG; both overlap the MMAs below
            if (pf) {
                const int ib = ii[k + 1];
                const float* xg = x + (size_t)t0 * IN_F + (size_t)ib * 32 + q * 4;
                const uint32_t xsd = smem_u32(xs[s ^ 1]);
#pragma unroll
                for (int jr = 0; jr < 8; ++jr) {
                    const int t = rg + 32 * jr;
                    cp16(xsd + (uint32_t)(t * XS_STRIDE + q * 4) * 4,
                         xg + (size_t)t * IN_F);
                }
                cp_commit();
                wv = ((const float4*)(w + (size_t)(k + 1) * 1024))[tid];
            }

            // ---- consume buffer s ----
            uint32_t B[32];
            {
                const uint32_t* wb = ws[s] + lane * WS_STRIDE;
#pragma unroll
                for (int h = 0; h < 8; ++h) {
                    const uint4 v = *(const uint4*)(wb + h * 4);
                    B[4 * h + 0] = v.x; B[4 * h + 1] = v.y;
                    B[4 * h + 2] = v.z; B[4 * h + 3] = v.w;
                }
            }
#pragma unroll
            for (int mt = 0; mt < 2; ++mt) {
                const int R0 = wid * 32 + mt * 16 + (lane >> 2);
                const float* xb = xs[s];
                uint32_t a0v[8], a1v[8];
#pragma unroll
                for (int jj = 0; jj < 8; ++jj)
                    a0v[jj] = f2tf(xb[R0 * XS_STRIDE + (lane & 3) + 4 * jj]);
#pragma unroll
                for (int jj = 0; jj < 8; ++jj)
                    a1v[jj] = f2tf(xb[(R0 + 8) * XS_STRIDE + (lane & 3) + 4 * jj]);
#pragma unroll
                for (int ks = 0; ks < 4; ++ks) {
#pragma unroll
                    for (int nt = 0; nt < 4; ++nt) {
                        mma_tf32(c[mt][nt][0], c[mt][nt][1], c[mt][nt][2], c[mt][nt][3],
                                 a0v[2 * ks], a1v[2 * ks], a0v[2 * ks + 1], a1v[2 * ks + 1],
                                 B[ks * 8 + nt * 2], B[ks * 8 + nt * 2 + 1]);
                    }
                }
            }

            // ---- finish producing buffer s^1 ----
            if (pf) {
                uint32_t* wd = ws[s ^ 1];
                wd[w_dst[0]] = f2tf(wv.x);
                wd[w_dst[1]] = f2tf(wv.y);
                wd[w_dst[2]] = f2tf(wv.z);
                wd[w_dst[3]] = f2tf(wv.w);
                cp_wait0();
            }
            __syncthreads();
        }
    }

    // ---------------- epilogue: C regs -> y (also writes zeros for empty obs) ----------------
#pragma unroll
    for (int mt = 0; mt < 2; ++mt) {
#pragma unroll
        for (int nt = 0; nt < 4; ++nt) {
            const int row = t0 + wid * 32 + mt * 16 + (lane >> 2);
            const int col = ob * 32 + nt * 8 + (lane & 3) * 2;
            float2 v0 = make_float2(c[mt][nt][0], c[mt][nt][1]);
            float2 v1 = make_float2(c[mt][nt][2], c[mt][nt][3]);
            *(float2*)(y + (size_t)row * OUT_F + col)       = v0;
            *(float2*)(y + (size_t)(row + 8) * OUT_F + col) = v1;
        }
    }
}

extern "C" void kernel_launch(void* const* d_in, const int* in_sizes, int n_in,
                              void* d_out, int out_size) {
    const float* x  = (const float*)d_in[0];
    const float* w  = (const float*)d_in[1];
    const int*   oi = (const int*)  d_in[2];
    const int*   ii = (const int*)  d_in[3];
    float*       y  = (float*)d_out;

    static int smem_set = 0;
    if (!smem_set) {
        cudaFuncSetAttribute(bsmm_mma_kernel,
                             cudaFuncAttributeMaxDynamicSharedMemorySize, SMEM_BYTES);
        smem_set = 1;
    }

    build_rowptr_kernel<<<1, 96>>>(oi);

    dim3 grid(OBLK, N_TOK / TILE_T);
    bsmm_mma_kernel<<<grid, THREADS, SMEM_BYTES>>>(x, w, ii, y);
}

// round 4
// speedup vs baseline: 3.0287x; 1.0685x over previous
#include <cuda_runtime.h>
#include <cstdint>

#define N_TOK   2048
#define IN_F    2048
#define OUT_F   2048
#define OBLK    64
#define NNZ     1228
#define TILE_T  128
#define THREADS 256
#define PIPE    3

#define XS_STRIDE 36                       // words per token row (144B, 16B-aligned, conflict-free)
#define XS_WORDS  (TILE_T * XS_STRIDE)     // 4608 words = 18432 B
#define WS_STRIDE 36
#define WS_WORDS  (32 * WS_STRIDE)         // 1152 words = 4608 B
#define SMEM_BYTES (PIPE * (XS_WORDS + WS_WORDS) * 4)   // 69120 B

__device__ int g_row_ptr[OBLK + 1];

__global__ void build_rowptr_kernel(const int* __restrict__ oi) {
    int b = threadIdx.x;
    if (b <= OBLK) {
        int lo = 0, hi = NNZ;
        while (lo < hi) { int m = (lo + hi) >> 1; if (oi[m] < b) lo = m + 1; else hi = m; }
        g_row_ptr[b] = lo;
    }
}

// ---------- helpers ----------
__device__ __forceinline__ uint32_t smem_u32(const void* p) {
    uint32_t a;
    asm("{ .reg .u64 t; cvta.to.shared.u64 t, %1; cvt.u32.u64 %0, t; }" : "=r"(a) : "l"(p));
    return a;
}
__device__ __forceinline__ uint32_t f2tf(float f) {
    uint32_t u; asm("cvt.rna.tf32.f32 %0, %1;" : "=r"(u) : "f"(f)); return u;
}
__device__ __forceinline__ void cp16(uint32_t dst, const void* src) {
    asm volatile("cp.async.cg.shared.global [%0], [%1], 16;" :: "r"(dst), "l"(src) : "memory");
}
__device__ __forceinline__ void cp_commit() { asm volatile("cp.async.commit_group;" ::: "memory"); }
__device__ __forceinline__ void cp_wait1()  { asm volatile("cp.async.wait_group 1;"  ::: "memory"); }

__device__ __forceinline__ void mma_tf32(float& c0, float& c1, float& c2, float& c3,
                                         uint32_t a0, uint32_t a1, uint32_t a2, uint32_t a3,
                                         uint32_t b0, uint32_t b1) {
    asm volatile("mma.sync.aligned.m16n8k8.row.col.f32.tf32.tf32.f32 "
                 "{%0,%1,%2,%3}, {%4,%5,%6,%7}, {%8,%9}, {%0,%1,%2,%3};"
                 : "+f"(c0), "+f"(c1), "+f"(c2), "+f"(c3)
                 : "r"(a0), "r"(a1), "r"(a2), "r"(a3), "r"(b0), "r"(b1));
}

// ---------- main kernel ----------
__global__ __launch_bounds__(THREADS, 3) void bsmm_mma_kernel(
    const float* __restrict__ x,
    const float* __restrict__ w,
    const int*   __restrict__ ii,
    float*       __restrict__ y)
{
    extern __shared__ float sm[];
    float*    xsb = sm;                                   // PIPE x-tile buffers
    uint32_t* wsb = (uint32_t*)(sm + PIPE * XS_WORDS);    // PIPE w buffers (tf32, fragment-ordered)

    const int ob   = blockIdx.x;
    const int t0   = blockIdx.y * TILE_T;
    const int tid  = threadIdx.x;
    const int wid  = tid >> 5;
    const int lane = tid & 31;
    const int q    = tid & 7;            // float4 column (0..7)
    const int rg   = tid >> 3;           // row group (0..31)

    const uint32_t xs_base = smem_u32(xsb);

    const int k0 = g_row_ptr[ob];
    const int k1 = g_row_ptr[ob + 1];
    const int nblk = k1 - k0;

    float c[4][4];
#pragma unroll
    for (int nt = 0; nt < 4; ++nt)
#pragma unroll
        for (int r = 0; r < 4; ++r) c[nt][r] = 0.0f;

    // w fragment-staging destinations for this thread's float4 (o = rg, i = q*4+cc)
    int w_dst[4];
#pragma unroll
    for (int cc = 0; cc < 4; ++cc) {
        const int i  = q * 4 + cc;
        const int dl = (rg & 7) * 4 + (i & 3);                    // dest lane
        const int j  = (i >> 3) * 8 + (rg >> 3) * 2 + ((i >> 2) & 1);
        w_dst[cc] = dl * WS_STRIDE + j;
    }

    if (nblk > 0) {
        // -------- prologue: stage tiles 0 and 1 --------
#pragma unroll
        for (int p = 0; p < 2; ++p) {
            if (p < nblk) {
                const int ib = ii[k0 + p];
                const float* xg = x + (size_t)t0 * IN_F + (size_t)ib * 32 + q * 4;
                const uint32_t xd = xs_base + (uint32_t)(p * XS_WORDS + q * 4) * 4;
#pragma unroll
                for (int jr = 0; jr < 4; ++jr) {
                    const int t = rg + 32 * jr;
                    cp16(xd + (uint32_t)(t * XS_STRIDE) * 4, xg + (size_t)t * IN_F);
                }
            }
            cp_commit();
        }
        {   // w tile 0: direct store
            const float4 wv = ((const float4*)(w + (size_t)k0 * 1024))[tid];
            wsb[w_dst[0]] = f2tf(wv.x); wsb[w_dst[1]] = f2tf(wv.y);
            wsb[w_dst[2]] = f2tf(wv.z); wsb[w_dst[3]] = f2tf(wv.w);
        }
        float4 wv_sts = make_float4(0.f, 0.f, 0.f, 0.f);
        if (nblk > 1) wv_sts = ((const float4*)(w + (size_t)(k0 + 1) * 1024))[tid];

        const int R0 = wid * 16 + (lane >> 2);
        const int kq = lane & 3;

        // -------- main loop --------
        for (int j = 0; j < nblk; ++j) {
            const int s = j % PIPE;

            cp_wait1();            // tile j resident (for this thread's copies)
            __syncthreads();       // visible to all; also retires consume of iter j-1

            // prefetch x tile j+2
            if (j + 2 < nblk) {
                const int ib = ii[k0 + j + 2];
                const float* xg = x + (size_t)t0 * IN_F + (size_t)ib * 32 + q * 4;
                const uint32_t xd = xs_base + (uint32_t)(((j + 2) % PIPE) * XS_WORDS + q * 4) * 4;
#pragma unroll
                for (int jr = 0; jr < 4; ++jr) {
                    const int t = rg + 32 * jr;
                    cp16(xd + (uint32_t)(t * XS_STRIDE) * 4, xg + (size_t)t * IN_F);
                }
            }
            cp_commit();           // unconditional: keeps group accounting exact

            // stage w tile j+1; start LDG of w tile j+2
            float4 wv_new = make_float4(0.f, 0.f, 0.f, 0.f);
            if (j + 2 < nblk) wv_new = ((const float4*)(w + (size_t)(j + 2 + k0) * 1024))[tid];
            if (j + 1 < nblk) {
                uint32_t* wd = wsb + ((j + 1) % PIPE) * WS_WORDS;
                wd[w_dst[0]] = f2tf(wv_sts.x); wd[w_dst[1]] = f2tf(wv_sts.y);
                wd[w_dst[2]] = f2tf(wv_sts.z); wd[w_dst[3]] = f2tf(wv_sts.w);
            }

            // ---- consume tile j ----
            const float*    xb = xsb + s * XS_WORDS;
            const uint32_t* wb = wsb + s * WS_WORDS + lane * WS_STRIDE;
#pragma unroll
            for (int ks = 0; ks < 4; ++ks) {
                const uint4 v0 = *(const uint4*)(wb + ks * 8);
                const uint4 v1 = *(const uint4*)(wb + ks * 8 + 4);
                const uint32_t a0 = f2tf(xb[ R0      * XS_STRIDE + kq + 8 * ks]);
                const uint32_t a1 = f2tf(xb[(R0 + 8) * XS_STRIDE + kq + 8 * ks]);
                const uint32_t a2 = f2tf(xb[ R0      * XS_STRIDE + kq + 8 * ks + 4]);
                const uint32_t a3 = f2tf(xb[(R0 + 8) * XS_STRIDE + kq + 8 * ks + 4]);
                mma_tf32(c[0][0], c[0][1], c[0][2], c[0][3], a0, a1, a2, a3, v0.x, v0.y);
                mma_tf32(c[1][0], c[1][1], c[1][2], c[1][3], a0, a1, a2, a3, v0.z, v0.w);
                mma_tf32(c[2][0], c[2][1], c[2][2], c[2][3], a0, a1, a2, a3, v1.x, v1.y);
                mma_tf32(c[3][0], c[3][1], c[3][2], c[3][3], a0, a1, a2, a3, v1.z, v1.w);
            }
            wv_sts = wv_new;
        }
    }

    // -------- epilogue (also writes zeros for empty output blocks) --------
#pragma unroll
    for (int nt = 0; nt < 4; ++nt) {
        const int row = t0 + wid * 16 + (lane >> 2);
        const int col = ob * 32 + nt * 8 + (lane & 3) * 2;
        *(float2*)(y + (size_t)row * OUT_F + col)       = make_float2(c[nt][0], c[nt][1]);
        *(float2*)(y + (size_t)(row + 8) * OUT_F + col) = make_float2(c[nt][2], c[nt][3]);
    }
}

extern "C" void kernel_launch(void* const* d_in, const int* in_sizes, int n_in,
                              void* d_out, int out_size) {
    const float* x  = (const float*)d_in[0];
    const float* w  = (const float*)d_in[1];
    const int*   oi = (const int*)  d_in[2];
    const int*   ii = (const int*)  d_in[3];
    float*       y  = (float*)d_out;

    static int smem_set = 0;
    if (!smem_set) {
        cudaFuncSetAttribute(bsmm_mma_kernel,
                             cudaFuncAttributeMaxDynamicSharedMemorySize, SMEM_BYTES);
        smem_set = 1;
    }

    build_rowptr_kernel<<<1, 96>>>(oi);

    dim3 grid(OBLK, N_TOK / TILE_T);
    bsmm_mma_kernel<<<grid, THREADS, SMEM_BYTES>>>(x, w, ii, y);
}